// round 6
// baseline (speedup 1.0000x reference)
#include <cuda_runtime.h>

// ---------------- problem constants ----------------
#define T_TOTAL 35968706LL          // sum of all 52 weight-tensor sizes
#define NV (T_TOTAL / 2)            // float2 count per row (T even)
#define ENC_BLOCKS 148
#define ENC_THREADS 256
#define ENC_NT (ENC_BLOCKS * ENC_THREADS)

// ---------------- device scratch (no allocs allowed) ----------------
__device__ float g_c1[4 * 4  * 112 * 112];
__device__ float g_c2[4 * 8  * 56  * 56];
__device__ float g_c3[4 * 16 * 28  * 28];
__device__ float g_c4[4 * 32 * 14  * 14];
__device__ float g_c5[4 * 64 * 7   * 7];
__device__ int   g_idx[4];
__device__ unsigned g_cnt[8];       // grid-barrier counters (reset by init_k each call)

// ---------------- init: zero barrier counters ----------------
__global__ void init_k() {
    if (threadIdx.x < 8) g_cnt[threadIdx.x] = 0u;
}

// ---------------- grid barrier (all ENC_BLOCKS co-resident) ----------------
__device__ __forceinline__ void grid_bar(int id) {
    __syncthreads();
    if (threadIdx.x == 0) {
        __threadfence();
        unsigned prev = atomicAdd(&g_cnt[id], 1u);
        if (prev + 1u < (unsigned)ENC_BLOCKS) {
            while (*((volatile unsigned*)&g_cnt[id]) < (unsigned)ENC_BLOCKS) { }
        }
        __threadfence();
    }
    __syncthreads();
}

// ---------------- one conv stage (k=4, s=2, p=1), grid-strided ----------------
__device__ __forceinline__ void conv_stage(
    const float* __restrict__ x, const float* __restrict__ w,
    const float* __restrict__ bias, float* __restrict__ y,
    int Cin, int Hin, int Win, int Cout, int Hout, int Wout, bool lrelu, int gtid)
{
    int total = 4 * Cout * Hout * Wout;
    for (int i = gtid; i < total; i += ENC_NT) {
        int ow = i % Wout; int t = i / Wout;
        int oh = t % Hout; t /= Hout;
        int co = t % Cout; int n = t / Cout;

        float acc = bias[co];
        const float* wc = w + co * Cin * 16;
        const float* xn = x + (long long)n * Cin * Hin * Win;
        int ih0 = oh * 2 - 1, iw0 = ow * 2 - 1;

        for (int ci = 0; ci < Cin; ci++) {
            const float* xc = xn + ci * Hin * Win;
            const float* wk = wc + ci * 16;
            #pragma unroll
            for (int kh = 0; kh < 4; kh++) {
                int ih = ih0 + kh;
                if ((unsigned)ih >= (unsigned)Hin) continue;
                const float* xr = xc + ih * Win;
                #pragma unroll
                for (int kw = 0; kw < 4; kw++) {
                    int iw = iw0 + kw;
                    if ((unsigned)iw < (unsigned)Win)
                        acc = fmaf(xr[iw], wk[kh * 4 + kw], acc);
                }
            }
        }
        if (lrelu) acc = (acc >= 0.f) ? acc : 0.01f * acc;
        y[i] = acc;
    }
}

// ---------------- fused encoder: 5 convs + head in one kernel ----------------
__global__ void __launch_bounds__(ENC_THREADS)
enc_k(const float* __restrict__ rgb,
      const float* __restrict__ cw1, const float* __restrict__ cb1,
      const float* __restrict__ cw2, const float* __restrict__ cb2,
      const float* __restrict__ cw3, const float* __restrict__ cb3,
      const float* __restrict__ cw4, const float* __restrict__ cb4,
      const float* __restrict__ cw5, const float* __restrict__ cb5,
      const float* __restrict__ fc1w, const float* __restrict__ fc1b,
      const float* __restrict__ fc2w, const float* __restrict__ fc2b,
      const float* __restrict__ emb,
      float* __restrict__ loss_out)
{
#if __CUDA_ARCH__ >= 900
    cudaTriggerProgrammaticLaunchCompletion();   // let the GEMM start immediately
#endif
    int gtid = blockIdx.x * ENC_THREADS + threadIdx.x;

    conv_stage(rgb,  cw1, cb1, g_c1, 3,  224, 224, 4,  112, 112, true,  gtid);
    grid_bar(0);
    conv_stage(g_c1, cw2, cb2, g_c2, 4,  112, 112, 8,  56,  56,  true,  gtid);
    grid_bar(1);
    conv_stage(g_c2, cw3, cb3, g_c3, 8,  56,  56,  16, 28,  28,  true,  gtid);
    grid_bar(2);
    conv_stage(g_c3, cw4, cb4, g_c4, 16, 28,  28,  32, 14,  14,  true,  gtid);
    grid_bar(3);
    conv_stage(g_c4, cw5, cb5, g_c5, 32, 14,  14,  64, 7,   7,   false, gtid);
    grid_bar(4);

    // ---- head: block 0 only ----
    if (blockIdx.x != 0) return;
    __shared__ float sx[4][64];
    __shared__ float sh[4][16];
    __shared__ float se[4][16];
    __shared__ int   sidx[4];
    __shared__ float sred[64];
    int tid = threadIdx.x;

    {   // adaptive avg pool 7x7
        int b = tid >> 6, c = tid & 63;
        const float* p = g_c5 + (b * 64 + c) * 49;
        float s = 0.f;
        #pragma unroll
        for (int i = 0; i < 49; i++) s += p[i];
        sx[b][c] = s * (1.f / 49.f);
    }
    __syncthreads();

    if (tid < 64) {   // fc1 + lrelu
        int b = tid >> 4, j = tid & 15;
        float s = fc1b[j];
        #pragma unroll
        for (int k = 0; k < 64; k++) s += sx[b][k] * fc1w[j * 64 + k];
        sh[b][j] = (s >= 0.f) ? s : 0.01f * s;
    }
    __syncthreads();

    if (tid < 64) {   // fc2
        int b = tid >> 4, j = tid & 15;
        float s = fc2b[j];
        #pragma unroll
        for (int k = 0; k < 16; k++) s += sh[b][k] * fc2w[j * 16 + k];
        se[b][j] = s;
    }
    __syncthreads();

    if (tid < 4) {    // VQ argmin (first-min like jnp.argmin)
        int b = tid;
        float ee = 0.f;
        #pragma unroll
        for (int j = 0; j < 16; j++) ee += se[b][j] * se[b][j];
        float best = __int_as_float(0x7f800000);
        int bi = 0;
        for (int c = 0; c < 4; c++) {
            float s2 = 0.f, dot = 0.f;
            #pragma unroll
            for (int j = 0; j < 16; j++) {
                float w = emb[c * 16 + j];
                s2  += w * w;
                dot += w * se[b][j];
            }
            float d = ee + s2 - 2.f * dot;
            if (d < best) { best = d; bi = c; }
        }
        sidx[b] = bi;
        g_idx[b] = bi;
    }
    __syncthreads();

    if (tid < 64) {   // loss = 1.25 * mean((q - e)^2)
        int b = tid >> 4, j = tid & 15;
        float qv = emb[sidx[b] * 16 + j];
        float diff = qv - se[b][j];
        sred[tid] = diff * diff;
    }
    __syncthreads();
    if (tid == 0) {
        float s = 0.f;
        for (int i = 0; i < 64; i++) s += sred[i];
        *loss_out = 1.25f * s * (1.f / 64.f);
    }
}

// ---------------- streaming GEMM on codebook rows + idx permute at store ----
__device__ __forceinline__ float2 pick2(float2 a, float2 b, float2 c, float2 d, int i) {
    float2 r = a;
    if (i == 1) r = b;
    if (i == 2) r = c;
    if (i == 3) r = d;
    return r;
}

__global__ void __launch_bounds__(256)
gemm_k(const float* __restrict__ W, const float* __restrict__ emb,
       float* __restrict__ out)
{
    __shared__ float sq[64];                 // 4 codebook rows x 16
    if (threadIdx.x < 64) sq[threadIdx.x] = emb[threadIdx.x];
    __syncthreads();

    long long i = (long long)blockIdx.x * blockDim.x + threadIdx.x;

    const float2* __restrict__ W2 = (const float2*)W;
    float2 a0 = {0.f,0.f}, a1 = {0.f,0.f}, a2 = {0.f,0.f}, a3 = {0.f,0.f};

    if (i < NV) {
        #pragma unroll
        for (int k = 0; k < 16; k++) {
            float2 w = __ldcs(&W2[(long long)k * NV + i]);
            float q0 = sq[k], q1 = sq[16 + k], q2 = sq[32 + k], q3 = sq[48 + k];
            a0.x = fmaf(q0, w.x, a0.x); a0.y = fmaf(q0, w.y, a0.y);
            a1.x = fmaf(q1, w.x, a1.x); a1.y = fmaf(q1, w.y, a1.y);
            a2.x = fmaf(q2, w.x, a2.x); a2.y = fmaf(q2, w.y, a2.y);
            a3.x = fmaf(q3, w.x, a3.x); a3.y = fmaf(q3, w.y, a3.y);
        }
    }

#if __CUDA_ARCH__ >= 900
    cudaGridDependencySynchronize();         // wait for encoder (idx) only now
#endif

    if (i >= NV) return;
    int i0 = *((volatile int*)&g_idx[0]);
    int i1 = *((volatile int*)&g_idx[1]);
    int i2 = *((volatile int*)&g_idx[2]);
    int i3 = *((volatile int*)&g_idx[3]);

    float2* __restrict__ O2 = (float2*)out;
    __stcs(&O2[i],          pick2(a0, a1, a2, a3, i0));
    __stcs(&O2[NV + i],     pick2(a0, a1, a2, a3, i1));
    __stcs(&O2[2 * NV + i], pick2(a0, a1, a2, a3, i2));
    __stcs(&O2[3 * NV + i], pick2(a0, a1, a2, a3, i3));
}

// ---------------- launch ----------------
extern "C" void kernel_launch(void* const* d_in, const int* in_sizes, int n_in,
                              void* d_out, int out_size)
{
    const float* rgb   = (const float*)d_in[0];
    const float* cw1   = (const float*)d_in[1];
    const float* cb1   = (const float*)d_in[2];
    const float* cw2   = (const float*)d_in[3];
    const float* cb2   = (const float*)d_in[4];
    const float* cw3   = (const float*)d_in[5];
    const float* cb3   = (const float*)d_in[6];
    const float* cw4   = (const float*)d_in[7];
    const float* cb4   = (const float*)d_in[8];
    const float* cw5   = (const float*)d_in[9];
    const float* cb5   = (const float*)d_in[10];
    const float* fc1w  = (const float*)d_in[11];
    const float* fc1b  = (const float*)d_in[12];
    const float* fc2w  = (const float*)d_in[13];
    const float* fc2b  = (const float*)d_in[14];
    const float* emb   = (const float*)d_in[15];
    const float* Wall  = (const float*)d_in[16];
    float* out = (float*)d_out;

    init_k<<<1, 32>>>();

    enc_k<<<ENC_BLOCKS, ENC_THREADS>>>(rgb, cw1, cb1, cw2, cb2, cw3, cb3,
                                       cw4, cb4, cw5, cb5, fc1w, fc1b,
                                       fc2w, fc2b, emb,
                                       out + (long long)out_size - 1);

    // GEMM with programmatic dependent launch: overlaps the encoder, syncs
    // only before its stores (idx dependency).
    const int TB = 256;
    long long nblocks = (NV + TB - 1) / TB;

    cudaLaunchConfig_t cfg = {};
    cfg.gridDim  = dim3((unsigned)nblocks, 1, 1);
    cfg.blockDim = dim3(TB, 1, 1);
    cfg.dynamicSmemBytes = 0;
    cfg.stream = 0;
    cudaLaunchAttribute attrs[1];
    attrs[0].id = cudaLaunchAttributeProgrammaticStreamSerialization;
    attrs[0].val.programmaticStreamSerializationAllowed = 1;
    cfg.attrs = attrs;
    cfg.numAttrs = 1;
    cudaLaunchKernelEx(&cfg, gemm_k, Wall, emb, out);
}

// round 8
// speedup vs baseline: 1.5650x; 1.5650x over previous
#include <cuda_runtime.h>

// ---------------- problem constants ----------------
#define T_TOTAL 35968706LL          // sum of all 52 weight-tensor sizes
#define NV (T_TOTAL / 2)            // float2 count per row (T even)
#define ENC_BLOCKS 148
#define ENC_THREADS 256
#define ENC_NT (ENC_BLOCKS * ENC_THREADS)

// ---------------- device scratch (no allocs allowed) ----------------
__device__ float g_c1[4 * 4  * 112 * 112];
__device__ float g_c2[4 * 8  * 56  * 56];
__device__ float g_c3[4 * 16 * 28  * 28];
__device__ float g_c4[4 * 32 * 14  * 14];
__device__ float g_c5[4 * 64 * 7   * 7];
__device__ float g_q[64];                 // q[b][j]
__device__ unsigned g_cnt[8];             // barrier arrive counters (self-reset)
__device__ unsigned g_epoch[8];           // barrier release epochs (monotonic)

// ---------------- self-resetting grid barrier ----------------
// All ENC_BLOCKS are co-resident (148 blocks <= 148 SMs, nothing else running).
// Each id is used exactly once per kernel launch. The counter returns to 0 by
// the last arriver; the epoch is monotonically increasing across graph replays,
// so no init kernel is needed and state is launch-invariant.
__device__ __forceinline__ void grid_bar(int id) {
    __syncthreads();
    if (threadIdx.x == 0) {
        __threadfence();
        unsigned my_epoch = *((volatile unsigned*)&g_epoch[id]);
        unsigned prev = atomicAdd(&g_cnt[id], 1u);
        if (prev == (unsigned)(ENC_BLOCKS - 1)) {
            atomicSub(&g_cnt[id], (unsigned)ENC_BLOCKS);   // reset for next launch
            atomicAdd(&g_epoch[id], 1u);                    // release
        } else {
            while (*((volatile unsigned*)&g_epoch[id]) == my_epoch) { }
        }
        __threadfence();
    }
    __syncthreads();
}

// ---------------- one conv stage (k=4, s=2, p=1), grid-strided ----------------
__device__ __forceinline__ void conv_stage(
    const float* __restrict__ x, const float* __restrict__ w,
    const float* __restrict__ bias, float* __restrict__ y,
    int Cin, int Hin, int Win, int Cout, int Hout, int Wout, bool lrelu, int gtid)
{
    int total = 4 * Cout * Hout * Wout;
    for (int i = gtid; i < total; i += ENC_NT) {
        int ow = i % Wout; int t = i / Wout;
        int oh = t % Hout; t /= Hout;
        int co = t % Cout; int n = t / Cout;

        float acc = bias[co];
        const float* wc = w + co * Cin * 16;
        const float* xn = x + (long long)n * Cin * Hin * Win;
        int ih0 = oh * 2 - 1, iw0 = ow * 2 - 1;

        for (int ci = 0; ci < Cin; ci++) {
            const float* xc = xn + ci * Hin * Win;
            const float* wk = wc + ci * 16;
            #pragma unroll
            for (int kh = 0; kh < 4; kh++) {
                int ih = ih0 + kh;
                if ((unsigned)ih >= (unsigned)Hin) continue;
                const float* xr = xc + ih * Win;
                #pragma unroll
                for (int kw = 0; kw < 4; kw++) {
                    int iw = iw0 + kw;
                    if ((unsigned)iw < (unsigned)Win)
                        acc = fmaf(xr[iw], wk[kh * 4 + kw], acc);
                }
            }
        }
        if (lrelu) acc = (acc >= 0.f) ? acc : 0.01f * acc;
        y[i] = acc;
    }
}

// ---------------- fused encoder: 5 convs + head, ONE kernel ----------------
__global__ void __launch_bounds__(ENC_THREADS)
enc_k(const float* __restrict__ rgb,
      const float* __restrict__ cw1, const float* __restrict__ cb1,
      const float* __restrict__ cw2, const float* __restrict__ cb2,
      const float* __restrict__ cw3, const float* __restrict__ cb3,
      const float* __restrict__ cw4, const float* __restrict__ cb4,
      const float* __restrict__ cw5, const float* __restrict__ cb5,
      const float* __restrict__ fc1w, const float* __restrict__ fc1b,
      const float* __restrict__ fc2w, const float* __restrict__ fc2b,
      const float* __restrict__ emb,
      float* __restrict__ loss_out)
{
    int gtid = blockIdx.x * ENC_THREADS + threadIdx.x;

    conv_stage(rgb,  cw1, cb1, g_c1, 3,  224, 224, 4,  112, 112, true,  gtid);
    grid_bar(0);
    conv_stage(g_c1, cw2, cb2, g_c2, 4,  112, 112, 8,  56,  56,  true,  gtid);
    grid_bar(1);
    conv_stage(g_c2, cw3, cb3, g_c3, 8,  56,  56,  16, 28,  28,  true,  gtid);
    grid_bar(2);
    conv_stage(g_c3, cw4, cb4, g_c4, 16, 28,  28,  32, 14,  14,  true,  gtid);
    grid_bar(3);
    conv_stage(g_c4, cw5, cb5, g_c5, 32, 14,  14,  64, 7,   7,   false, gtid);
    grid_bar(4);

    // ---- head: block 0 only; all other blocks exit ----
    if (blockIdx.x != 0) return;
    __shared__ float sx[4][64];
    __shared__ float sh[4][16];
    __shared__ float se[4][16];
    __shared__ int   sidx[4];
    __shared__ float sred[64];
    int tid = threadIdx.x;

    {   // adaptive avg pool 7x7
        int b = tid >> 6, c = tid & 63;
        const float* p = g_c5 + (b * 64 + c) * 49;
        float s = 0.f;
        #pragma unroll
        for (int i = 0; i < 49; i++) s += p[i];
        sx[b][c] = s * (1.f / 49.f);
    }
    __syncthreads();

    if (tid < 64) {   // fc1 (64->16) + lrelu
        int b = tid >> 4, j = tid & 15;
        float s = fc1b[j];
        #pragma unroll
        for (int k = 0; k < 64; k++) s += sx[b][k] * fc1w[j * 64 + k];
        sh[b][j] = (s >= 0.f) ? s : 0.01f * s;
    }
    __syncthreads();

    if (tid < 64) {   // fc2 (16->16)
        int b = tid >> 4, j = tid & 15;
        float s = fc2b[j];
        #pragma unroll
        for (int k = 0; k < 16; k++) s += sh[b][k] * fc2w[j * 16 + k];
        se[b][j] = s;
    }
    __syncthreads();

    if (tid < 4) {    // VQ argmin (first-min like jnp.argmin)
        int b = tid;
        float ee = 0.f;
        #pragma unroll
        for (int j = 0; j < 16; j++) ee += se[b][j] * se[b][j];
        float best = __int_as_float(0x7f800000);
        int bi = 0;
        for (int c = 0; c < 4; c++) {
            float s2 = 0.f, dot = 0.f;
            #pragma unroll
            for (int j = 0; j < 16; j++) {
                float w = emb[c * 16 + j];
                s2  += w * w;
                dot += w * se[b][j];
            }
            float d = ee + s2 - 2.f * dot;
            if (d < best) { best = d; bi = c; }
        }
        sidx[b] = bi;
    }
    __syncthreads();

    if (tid < 64) {   // q to global + loss = 1.25 * mean((q - e)^2)
        int b = tid >> 4, j = tid & 15;
        float qv = emb[sidx[b] * 16 + j];
        g_q[tid] = qv;
        float diff = qv - se[b][j];
        sred[tid] = diff * diff;
    }
    __syncthreads();
    if (tid == 0) {
        float s = 0.f;
        for (int i = 0; i < 64; i++) s += sred[i];
        *loss_out = 1.25f * s * (1.f / 64.f);
    }
}

// ---------------- the big streaming GEMM: out = q @ W_all (R4-verified) ----
__global__ void __launch_bounds__(256)
gemm_k(const float* __restrict__ W, float* __restrict__ out)
{
    __shared__ float sq[64];
    if (threadIdx.x < 64) sq[threadIdx.x] = g_q[threadIdx.x];
    __syncthreads();

    long long i = (long long)blockIdx.x * blockDim.x + threadIdx.x;
    if (i >= NV) return;

    const float2* __restrict__ W2 = (const float2*)W;
    float2 a0 = {0.f, 0.f}, a1 = {0.f, 0.f}, a2 = {0.f, 0.f}, a3 = {0.f, 0.f};

    #pragma unroll
    for (int k = 0; k < 16; k++) {
        float2 w = __ldcs(&W2[(long long)k * NV + i]);
        float q0 = sq[k], q1 = sq[16 + k], q2 = sq[32 + k], q3 = sq[48 + k];
        a0.x = fmaf(q0, w.x, a0.x); a0.y = fmaf(q0, w.y, a0.y);
        a1.x = fmaf(q1, w.x, a1.x); a1.y = fmaf(q1, w.y, a1.y);
        a2.x = fmaf(q2, w.x, a2.x); a2.y = fmaf(q2, w.y, a2.y);
        a3.x = fmaf(q3, w.x, a3.x); a3.y = fmaf(q3, w.y, a3.y);
    }

    float2* __restrict__ O2 = (float2*)out;
    __stcs(&O2[i],          a0);
    __stcs(&O2[NV + i],     a1);
    __stcs(&O2[2 * NV + i], a2);
    __stcs(&O2[3 * NV + i], a3);
}

// ---------------- launch ----------------
extern "C" void kernel_launch(void* const* d_in, const int* in_sizes, int n_in,
                              void* d_out, int out_size)
{
    const float* rgb   = (const float*)d_in[0];
    const float* cw1   = (const float*)d_in[1];
    const float* cb1   = (const float*)d_in[2];
    const float* cw2   = (const float*)d_in[3];
    const float* cb2   = (const float*)d_in[4];
    const float* cw3   = (const float*)d_in[5];
    const float* cb3   = (const float*)d_in[6];
    const float* cw4   = (const float*)d_in[7];
    const float* cb4   = (const float*)d_in[8];
    const float* cw5   = (const float*)d_in[9];
    const float* cb5   = (const float*)d_in[10];
    const float* fc1w  = (const float*)d_in[11];
    const float* fc1b  = (const float*)d_in[12];
    const float* fc2w  = (const float*)d_in[13];
    const float* fc2b  = (const float*)d_in[14];
    const float* emb   = (const float*)d_in[15];
    const float* Wall  = (const float*)d_in[16];
    float* out = (float*)d_out;

    // one fused encoder kernel (serial, cooperative, self-resetting barriers)
    enc_k<<<ENC_BLOCKS, ENC_THREADS>>>(rgb, cw1, cb1, cw2, cb2, cw3, cb3,
                                       cw4, cb4, cw5, cb5, fc1w, fc1b,
                                       fc2w, fc2b, emb,
                                       out + (long long)out_size - 1);

    // big streaming GEMM (unchanged from the 454.8us best)
    const int TB = 256;
    long long nblocks = (NV + TB - 1) / TB;
    gemm_k<<<(unsigned)nblocks, TB>>>(Wall, out);
}

// round 9
// speedup vs baseline: 1.7507x; 1.1187x over previous
#include <cuda_runtime.h>

// ---------------- problem constants ----------------
#define T_TOTAL 35968706LL          // sum of all 52 weight-tensor sizes
#define NV (T_TOTAL / 2)            // float2 count per row (T even)
#define ENC_BLOCKS 592              // 4 blocks/SM on 148 SMs; all co-resident
#define ENC_THREADS 256
#define ENC_NT (ENC_BLOCKS * ENC_THREADS)   // 151,552 threads

// ---------------- device scratch (no allocs allowed) ----------------
__device__ float g_c1[4 * 4  * 112 * 112];
__device__ float g_c2[4 * 8  * 56  * 56];
__device__ float g_c3[4 * 16 * 28  * 28];
__device__ float g_c4[4 * 32 * 14  * 14];
__device__ float g_c5[4 * 64 * 7   * 7];
__device__ float g_q[64];                 // q[b][j]
__device__ unsigned g_cnt[8];             // barrier arrive counters (self-reset)
__device__ unsigned g_epoch[8];           // barrier release epochs (monotonic)

// ---------------- self-resetting grid barrier ----------------
// All ENC_BLOCKS co-resident (592 <= 148 SMs x >=5 blocks/SM capacity at these
// regs/threads). Counter self-resets; epoch is monotonic across graph replays,
// so no init kernel is needed and state is launch-invariant.
__device__ __forceinline__ void grid_bar(int id) {
    __syncthreads();
    if (threadIdx.x == 0) {
        __threadfence();
        unsigned my_epoch = *((volatile unsigned*)&g_epoch[id]);
        unsigned prev = atomicAdd(&g_cnt[id], 1u);
        if (prev == (unsigned)(ENC_BLOCKS - 1)) {
            atomicSub(&g_cnt[id], (unsigned)ENC_BLOCKS);   // reset for next launch
            atomicAdd(&g_epoch[id], 1u);                    // release
        } else {
            while (*((volatile unsigned*)&g_epoch[id]) == my_epoch) { }
        }
        __threadfence();
    }
    __syncthreads();
}

// ---------------- conv stage (k=4,s=2,p=1) with L-lane cooperation ----------
// L lanes (consecutive in a warp, L divides 32) cooperate on one output, each
// covering CIN/L input channels; partials combined by shfl_xor reduce.
// Loop structure is warp-converged: all threads run the same trip count and
// predicate loads/stores, so full-mask shfl is safe.
template<int CIN, int L, bool LRELU>
__device__ __forceinline__ void conv_stage(
    const float* __restrict__ x, const float* __restrict__ w,
    const float* __restrict__ bias, float* __restrict__ y,
    int Hin, int Win, int Cout, int Hout, int Wout, int gt)
{
    constexpr int CPL = CIN / L;          // channels per lane (all uses divide)
    const int sub   = gt % L;
    const int slot0 = gt / L;
    const int SLOTS = ENC_NT / L;
    const int total = 4 * Cout * Hout * Wout;

    for (int base = 0; base < total; base += SLOTS) {
        int slot = slot0 + base;
        bool active = (slot < total);
        int s = active ? slot : 0;        // safe dummy for inactive lanes

        int ow = s % Wout; int t = s / Wout;
        int oh = t % Hout; t /= Hout;
        int co = t % Cout; int n = t / Cout;

        int ih0 = oh * 2 - 1, iw0 = ow * 2 - 1;
        const float* xn = x + ((long long)n * CIN + sub * CPL) * Hin * Win;
        const float* wc = w + ((long long)co * CIN + sub * CPL) * 16;

        float acc = 0.f;
        if (active) {
            #pragma unroll
            for (int ci = 0; ci < CPL; ci++) {
                const float* xc = xn + ci * Hin * Win;
                const float* wk = wc + ci * 16;
                #pragma unroll
                for (int kh = 0; kh < 4; kh++) {
                    int ih = ih0 + kh;
                    if ((unsigned)ih >= (unsigned)Hin) continue;
                    const float* xr = xc + ih * Win;
                    #pragma unroll
                    for (int kw = 0; kw < 4; kw++) {
                        int iw = iw0 + kw;
                        if ((unsigned)iw < (unsigned)Win)
                            acc = fmaf(xr[iw], wk[kh * 4 + kw], acc);
                    }
                }
            }
        }
        // combine L partials (no-op when L==1)
        #pragma unroll
        for (int off = L / 2; off > 0; off >>= 1)
            acc += __shfl_xor_sync(0xffffffffu, acc, off);

        if (active && sub == 0) {
            acc += bias[co];
            if (LRELU) acc = (acc >= 0.f) ? acc : 0.01f * acc;
            y[slot] = acc;
        }
    }
}

// ---------------- fused encoder: 5 convs + head, ONE kernel ----------------
__global__ void __launch_bounds__(ENC_THREADS, 4)
enc_k(const float* __restrict__ rgb,
      const float* __restrict__ cw1, const float* __restrict__ cb1,
      const float* __restrict__ cw2, const float* __restrict__ cb2,
      const float* __restrict__ cw3, const float* __restrict__ cb3,
      const float* __restrict__ cw4, const float* __restrict__ cb4,
      const float* __restrict__ cw5, const float* __restrict__ cb5,
      const float* __restrict__ fc1w, const float* __restrict__ fc1b,
      const float* __restrict__ fc2w, const float* __restrict__ fc2b,
      const float* __restrict__ emb,
      float* __restrict__ loss_out)
{
    int gt = blockIdx.x * ENC_THREADS + threadIdx.x;

    conv_stage<3, 1, true >(rgb,  cw1, cb1, g_c1, 224, 224, 4,  112, 112, gt);
    grid_bar(0);
    conv_stage<4, 1, true >(g_c1, cw2, cb2, g_c2, 112, 112, 8,  56,  56,  gt);
    grid_bar(1);
    conv_stage<8, 2, true >(g_c2, cw3, cb3, g_c3, 56,  56,  16, 28,  28,  gt);
    grid_bar(2);
    conv_stage<16,4, true >(g_c3, cw4, cb4, g_c4, 28,  28,  32, 14,  14,  gt);
    grid_bar(3);
    conv_stage<32,8, false>(g_c4, cw5, cb5, g_c5, 14,  14,  64, 7,   7,   gt);
    grid_bar(4);

    // ---- head: block 0 only; all other blocks exit ----
    if (blockIdx.x != 0) return;
    __shared__ float sx[4][64];
    __shared__ float sh[4][16];
    __shared__ float se[4][16];
    __shared__ int   sidx[4];
    __shared__ float sred[64];
    int tid = threadIdx.x;

    {   // adaptive avg pool 7x7
        int b = tid >> 6, c = tid & 63;
        const float* p = g_c5 + (b * 64 + c) * 49;
        float s = 0.f;
        #pragma unroll
        for (int i = 0; i < 49; i++) s += p[i];
        sx[b][c] = s * (1.f / 49.f);
    }
    __syncthreads();

    if (tid < 64) {   // fc1 (64->16) + lrelu
        int b = tid >> 4, j = tid & 15;
        float s = fc1b[j];
        #pragma unroll
        for (int k = 0; k < 64; k++) s += sx[b][k] * fc1w[j * 64 + k];
        sh[b][j] = (s >= 0.f) ? s : 0.01f * s;
    }
    __syncthreads();

    if (tid < 64) {   // fc2 (16->16)
        int b = tid >> 4, j = tid & 15;
        float s = fc2b[j];
        #pragma unroll
        for (int k = 0; k < 16; k++) s += sh[b][k] * fc2w[j * 16 + k];
        se[b][j] = s;
    }
    __syncthreads();

    if (tid < 4) {    // VQ argmin (first-min like jnp.argmin)
        int b = tid;
        float ee = 0.f;
        #pragma unroll
        for (int j = 0; j < 16; j++) ee += se[b][j] * se[b][j];
        float best = __int_as_float(0x7f800000);
        int bi = 0;
        for (int c = 0; c < 4; c++) {
            float s2 = 0.f, dot = 0.f;
            #pragma unroll
            for (int j = 0; j < 16; j++) {
                float w = emb[c * 16 + j];
                s2  += w * w;
                dot += w * se[b][j];
            }
            float d = ee + s2 - 2.f * dot;
            if (d < best) { best = d; bi = c; }
        }
        sidx[b] = bi;
    }
    __syncthreads();

    if (tid < 64) {   // q to global + loss = 1.25 * mean((q - e)^2)
        int b = tid >> 4, j = tid & 15;
        float qv = emb[sidx[b] * 16 + j];
        g_q[tid] = qv;
        float diff = qv - se[b][j];
        sred[tid] = diff * diff;
    }
    __syncthreads();
    if (tid == 0) {
        float s = 0.f;
        for (int i = 0; i < 64; i++) s += sred[i];
        *loss_out = 1.25f * s * (1.f / 64.f);
    }
}

// ---------------- the big streaming GEMM: out = q @ W_all (R4-verified) ----
__global__ void __launch_bounds__(256)
gemm_k(const float* __restrict__ W, float* __restrict__ out)
{
    __shared__ float sq[64];
    if (threadIdx.x < 64) sq[threadIdx.x] = g_q[threadIdx.x];
    __syncthreads();

    long long i = (long long)blockIdx.x * blockDim.x + threadIdx.x;
    if (i >= NV) return;

    const float2* __restrict__ W2 = (const float2*)W;
    float2 a0 = {0.f, 0.f}, a1 = {0.f, 0.f}, a2 = {0.f, 0.f}, a3 = {0.f, 0.f};

    #pragma unroll
    for (int k = 0; k < 16; k++) {
        float2 w = __ldcs(&W2[(long long)k * NV + i]);
        float q0 = sq[k], q1 = sq[16 + k], q2 = sq[32 + k], q3 = sq[48 + k];
        a0.x = fmaf(q0, w.x, a0.x); a0.y = fmaf(q0, w.y, a0.y);
        a1.x = fmaf(q1, w.x, a1.x); a1.y = fmaf(q1, w.y, a1.y);
        a2.x = fmaf(q2, w.x, a2.x); a2.y = fmaf(q2, w.y, a2.y);
        a3.x = fmaf(q3, w.x, a3.x); a3.y = fmaf(q3, w.y, a3.y);
    }

    float2* __restrict__ O2 = (float2*)out;
    __stcs(&O2[i],          a0);
    __stcs(&O2[NV + i],     a1);
    __stcs(&O2[2 * NV + i], a2);
    __stcs(&O2[3 * NV + i], a3);
}

// ---------------- launch ----------------
extern "C" void kernel_launch(void* const* d_in, const int* in_sizes, int n_in,
                              void* d_out, int out_size)
{
    const float* rgb   = (const float*)d_in[0];
    const float* cw1   = (const float*)d_in[1];
    const float* cb1   = (const float*)d_in[2];
    const float* cw2   = (const float*)d_in[3];
    const float* cb2   = (const float*)d_in[4];
    const float* cw3   = (const float*)d_in[5];
    const float* cb3   = (const float*)d_in[6];
    const float* cw4   = (const float*)d_in[7];
    const float* cb4   = (const float*)d_in[8];
    const float* cw5   = (const float*)d_in[9];
    const float* cb5   = (const float*)d_in[10];
    const float* fc1w  = (const float*)d_in[11];
    const float* fc1b  = (const float*)d_in[12];
    const float* fc2w  = (const float*)d_in[13];
    const float* fc2b  = (const float*)d_in[14];
    const float* emb   = (const float*)d_in[15];
    const float* Wall  = (const float*)d_in[16];
    float* out = (float*)d_out;

    // one fused encoder kernel (serial, cooperative, self-resetting barriers)
    enc_k<<<ENC_BLOCKS, ENC_THREADS>>>(rgb, cw1, cb1, cw2, cb2, cw3, cb3,
                                       cw4, cb4, cw5, cb5, fc1w, fc1b,
                                       fc2w, fc2b, emb,
                                       out + (long long)out_size - 1);

    // big streaming GEMM (unchanged from the 454.8us best)
    const int TB = 256;
    long long nblocks = (NV + TB - 1) / TB;
    gemm_k<<<(unsigned)nblocks, TB>>>(Wall, out);
}